// round 13
// baseline (speedup 1.0000x reference)
#include <cuda_runtime.h>
#include <cuda_bf16.h>
#include <stdint.h>
#include <math.h>

// ---------------- problem constants ----------------
#define PB   100
#define NRT  2048
#define NCAP 10
#define DI   8
#define DO   16
#define KTOT 20736        // 256*81
#define NIT  162          // GEMM per-CTA iterations

// primary squash consts
#define P_T1 (-13.46416092f)
#define P_A1 (0.000242759f)
#define P_B1 (0.024488359f)
#define P_A2 (0.002769205f)
#define P_B2 (0.06089699f)
#define P_T3 (13.23405266f)
#define P_A3 (-0.002828244f)
#define P_B3 (0.061313814f)
#define P_A4 (-0.000219038f)
#define P_B4 (0.023874787f)
// digit squash consts
#define D_T1 (-0.075410217f)
#define D_A1 (-0.074520095f)
#define D_B1 (0.349297946f)
#define D_A2 (-0.534473989f)
#define D_B2 (0.27196494f)
#define D_T3 (0.062207676f)
#define D_A3 (0.637642944f)
#define D_B3 (0.295330779f)
#define D_A4 (0.169344703f)
#define D_B4 (0.353784456f)

// ---------------- scratch ----------------
__device__ __align__(256) __nv_bfloat16 g_xth[(size_t)PB*576*256];
__device__ __align__(256) __nv_bfloat16 g_xtl[(size_t)PB*576*256];
__device__ __align__(256) __nv_bfloat16 g_wh[(size_t)256*KTOT];
__device__ __align__(256) __nv_bfloat16 g_wl[(size_t)256*KTOT];
__device__ float g_u[PB*NRT*DI];
__device__ float g_up[2*PB*NRT*DI];
__device__ __align__(16) float g_us[PB*NRT*DI];         // mag*u, [b][r][i]
__device__ float g_spart[(size_t)128*PB*NCAP*DO];       // sj partials
__device__ float g_bij[NRT*NCAP];
__device__ __align__(16) float g_vj[PB*NCAP*DO];
__device__ float g_h1[PB*512];
__device__ float g_h2[PB*1024];

// ---------------- PTX helpers (base sm_80 features only) ----------------
__device__ __forceinline__ uint32_t s2u(const void* p) {
    uint32_t a;
    asm("{ .reg .u64 t; cvta.to.shared.u64 t, %1; cvt.u32.u64 %0, t; }"
        : "=r"(a) : "l"(p));
    return a;
}
__device__ __forceinline__ void cpa16(uint32_t dst, const void* src) {
    asm volatile("cp.async.cg.shared.global [%0], [%1], 16;"
                 :: "r"(dst), "l"(src) : "memory");
}
__device__ __forceinline__ void ldsm4(uint32_t* r, uint32_t addr) {
    asm volatile("ldmatrix.sync.aligned.m8n8.x4.shared.b16 {%0,%1,%2,%3}, [%4];"
                 : "=r"(r[0]), "=r"(r[1]), "=r"(r[2]), "=r"(r[3]) : "r"(addr));
}
__device__ __forceinline__ void mma16816(float* d, const uint32_t* a, const uint32_t* b) {
    asm volatile("mma.sync.aligned.m16n8k16.row.col.f32.bf16.bf16.f32 "
                 "{%0,%1,%2,%3}, {%4,%5,%6,%7}, {%8,%9}, {%0,%1,%2,%3};"
                 : "+f"(d[0]), "+f"(d[1]), "+f"(d[2]), "+f"(d[3])
                 : "r"(a[0]), "r"(a[1]), "r"(a[2]), "r"(a[3]),
                   "r"(b[0]), "r"(b[1]));
}
#define SWZ(o) ((o) ^ (((o) >> 3) & 0x70))

#define STG 49152
#define SMEM_TOTAL (2*STG)
#define SJ_F  (20480 + 13600 + 160 + 16 + 16 + 2816)
#define SJ_SMEM (SJ_F * 4)                               // 148352
#define AG_SMEM ((10240 + 6800 + 16400 + 256) * 4)       // 134784
// conv1 fused smem (floats): img 1056 | ws 2592 | bs 32 | xs 18464
#define CV_SMEM ((1056 + 2592 + 32 + 18464) * 4)         // 88576

// ---------------- init b_ij (also ncu slot filler) ----------------
__global__ void initbij_kernel() {
    int i = blockIdx.x * blockDim.x + threadIdx.x;
    if (i < NRT * NCAP) g_bij[i] = 0.f;
}

// ---------------- weight split (hi+lo merged) ----------------
__global__ void wsplit_kernel(const float* __restrict__ w) {
    extern __shared__ float row[];
    int n = blockIdx.x, tid = threadIdx.x;
    for (int i = tid; i < KTOT; i += 256) row[i] = w[(size_t)n * KTOT + i];
    __syncthreads();
    for (int j = tid; j < KTOT; j += 256) {
        int kk = j >> 8, ci = j & 255;
        float x = row[ci * 81 + kk];
        __nv_bfloat16 h = __float2bfloat16(x);
        g_wh[(size_t)n * KTOT + j] = h;
        g_wl[(size_t)n * KTOT + j] = __float2bfloat16(x - __bfloat162float(h));
    }
}

// ---------------- conv1 + relu + transpose + bf16 split (fused) ----------------
// block (b, cg): 256 threads. thread -> (c = tid>>3, h = (tid&7)+8r), 24 w outputs in regs.
__global__ void __launch_bounds__(256, 2)
conv1_kernel(const float* __restrict__ data,
             const float* __restrict__ w,
             const float* __restrict__ bias) {
    extern __shared__ float cs[];
    float* img = cs;            // 32 rows x 33
    float* ws  = cs + 1056;     // 32*81
    float* bs  = cs + 3648;     // 32
    float* xs  = cs + 3680;     // 32*577
    int b = blockIdx.x, cg = blockIdx.y, tid = threadIdx.x;

    for (int i = tid; i < 1024; i += 256)
        img[(i >> 5) * 33 + (i & 31)] = data[b * 1024 + i];
    for (int i = tid; i < 32 * 81; i += 256) ws[i] = w[(cg * 32) * 81 + i];
    if (tid < 32) bs[tid] = bias[cg * 32 + tid];
    __syncthreads();

    int c = tid >> 3, hb = tid & 7;
    const float* wc = &ws[c * 81];
    for (int r = 0; r < 3; r++) {
        int h = hb + 8 * r;
        float acc[24];
        float bv = bs[c];
        #pragma unroll
        for (int q = 0; q < 24; q++) acc[q] = bv;
        for (int kh = 0; kh < 9; kh++) {
            float iv[32];
            const float* ir = &img[(h + kh) * 33];
            #pragma unroll
            for (int q = 0; q < 32; q++) iv[q] = ir[q];
            const float* wr = &wc[kh * 9];
            #pragma unroll
            for (int kw = 0; kw < 9; kw++) {
                float wv = wr[kw];
                #pragma unroll
                for (int q = 0; q < 24; q++) acc[q] += wv * iv[q + kw];
            }
        }
        float* xr = &xs[c * 577 + h * 24];
        #pragma unroll
        for (int q = 0; q < 24; q++) xr[q] = fmaxf(acc[q], 0.f);
    }
    __syncthreads();

    // transpose + split (coalesced writes)
    for (int j = tid; j < 576 * 32; j += 256) {
        int rc = j >> 5, ci = j & 31;
        float x = xs[ci * 577 + rc];
        __nv_bfloat16 hh = __float2bfloat16(x);
        size_t o = ((size_t)b * 576 + rc) * 256 + cg * 32 + ci;
        g_xth[o] = hh;
        g_xtl[o] = __float2bfloat16(x - __bfloat162float(hh));
    }
}

// ---------------- GEMM stage loader ----------------
__device__ __forceinline__ void load_stage(int tid, int it, int kz, int bn,
                                           uint32_t sb,
                                           const __nv_bfloat16* __restrict__ xh,
                                           const __nv_bfloat16* __restrict__ xl) {
    int kk = it >> 1, ci0 = kz * 128 + (it & 1) * 64;
    int kh = kk / 9, kw = kk - kh * 9;
    #pragma unroll
    for (int j = 0; j < 12; j++) {
        int c = tid + 256 * j;
        if (c < 1024) {
            int half = c >> 9, cc = c & 511;
            int row = cc >> 3, col = cc & 7;
            int rc = ((row >> 3) * 2 + kh) * 24 + (row & 7) * 2 + kw;
            const __nv_bfloat16* src = (half ? xl : xh)
                                       + (size_t)rc * 256 + ci0 + col * 8;
            uint32_t dst = sb + half * 8192 + SWZ(row * 128 + col * 16);
            cpa16(dst, src);
        } else {
            int cc = c - 1024;
            int half = cc >> 10; cc &= 1023;
            int row = cc >> 3, col = cc & 7;
            int n = bn * 128 + row;
            const __nv_bfloat16* src = (half ? g_wl : g_wh)
                                       + (size_t)n * KTOT + kk * 256 + ci0 + col * 8;
            uint32_t dst = sb + 16384 + half * 16384 + SWZ(row * 128 + col * 16);
            cpa16(dst, src);
        }
    }
    asm volatile("cp.async.commit_group;" ::: "memory");
}

// ---------------- prim conv: mma.sync bf16-split implicit GEMM ----------------
__global__ void __launch_bounds__(256, 2)
prim_mma_kernel() {
    extern __shared__ char smc[];
    uint32_t smb = s2u(smc);
    int tid = threadIdx.x, lane = tid & 31, wid = tid >> 5;
    int wm = wid >> 2, wn = wid & 3;
    int b = blockIdx.x, bn = blockIdx.y, kz = blockIdx.z;
    const __nv_bfloat16* xh = g_xth + (size_t)b * (576 * 256);
    const __nv_bfloat16* xl = g_xtl + (size_t)b * (576 * 256);

    float acc[2][4][4];
    #pragma unroll
    for (int f = 0; f < 2; f++)
        #pragma unroll
        for (int nt = 0; nt < 4; nt++)
            #pragma unroll
            for (int q = 0; q < 4; q++) acc[f][nt][q] = 0.f;

    load_stage(tid, 0, kz, bn, smb, xh, xl);

    for (int it = 0; it < NIT; it++) {
        uint32_t sb = smb + (it & 1) * STG;
        if (it + 1 < NIT) {
            load_stage(tid, it + 1, kz, bn, smb + ((it + 1) & 1) * STG, xh, xl);
            asm volatile("cp.async.wait_group 1;" ::: "memory");
        } else {
            asm volatile("cp.async.wait_group 0;" ::: "memory");
        }
        __syncthreads();

        uint32_t sA = sb, sAl = sb + 8192, sB = sb + 16384, sBl = sb + 32768;
        #pragma unroll
        for (int ks = 0; ks < 4; ks++) {
            uint32_t ah[2][4], al[2][4], bh[4][2], bl[4][2];
            #pragma unroll
            for (int f = 0; f < 2; f++) {
                int row = wm * 32 + f * 16 + (lane & 15);
                int off = row * 128 + ks * 32 + (lane >> 4) * 16;
                uint32_t so = SWZ(off);
                ldsm4(ah[f], sA + so);
                ldsm4(al[f], sAl + so);
            }
            #pragma unroll
            for (int p = 0; p < 2; p++) {
                int row = wn * 32 + p * 16 + (lane & 7) + ((lane >> 4) << 3);
                int off = row * 128 + ks * 32 + ((lane >> 3) & 1) * 16;
                uint32_t so = SWZ(off);
                uint32_t th[4], tl[4];
                ldsm4(th, sB + so);
                ldsm4(tl, sBl + so);
                bh[2*p][0] = th[0]; bh[2*p][1] = th[1];
                bh[2*p+1][0] = th[2]; bh[2*p+1][1] = th[3];
                bl[2*p][0] = tl[0]; bl[2*p][1] = tl[1];
                bl[2*p+1][0] = tl[2]; bl[2*p+1][1] = tl[3];
            }
            #pragma unroll
            for (int f = 0; f < 2; f++)
                #pragma unroll
                for (int nt = 0; nt < 4; nt++) {
                    mma16816(acc[f][nt], ah[f], bh[nt]);
                    mma16816(acc[f][nt], ah[f], bl[nt]);
                    mma16816(acc[f][nt], al[f], bh[nt]);
                }
        }
        __syncthreads();
    }

    int tq = lane >> 2, tr = lane & 3;
    float* ob = g_up + (size_t)kz * (PB * NRT * DI) + (size_t)b * 16384;
    #pragma unroll
    for (int f = 0; f < 2; f++) {
        int ml = wm * 32 + f * 16 + tq;
        int h0 = ml >> 3, w0 = ml & 7;
        int mh = ml + 8;
        int h1 = mh >> 3, w1 = mh & 7;
        #pragma unroll
        for (int nt = 0; nt < 4; nt++) {
            int n0 = bn * 128 + wn * 32 + nt * 8 + tr * 2;
            ob[(size_t)n0 * 64 + h0 * 8 + w0]       = acc[f][nt][0];
            ob[(size_t)(n0 + 1) * 64 + h0 * 8 + w0] = acc[f][nt][1];
            ob[(size_t)n0 * 64 + h1 * 8 + w1]       = acc[f][nt][2];
            ob[(size_t)(n0 + 1) * 64 + h1 * 8 + w1] = acc[f][nt][3];
        }
    }
}

// ---------------- combine + primary squash + us (fused) ----------------
__global__ void mag_kernel(const float* __restrict__ bias) {
    int b = blockIdx.x;
    __shared__ float sv[2048];
    __shared__ short si[2048];
    __shared__ int cnt;
    int tid = threadIdx.x;   // 1024
    // phase A: combine K-split partials + bias -> g_u; keep component 0 in sv
    for (int i = tid; i < 16384; i += 1024) {
        float v = g_up[(size_t)b * 16384 + i]
                + g_up[(size_t)PB * NRT * DI + (size_t)b * 16384 + i]
                + bias[i >> 6];
        g_u[(size_t)b * 16384 + i] = v;
        if ((i & 7) == 0) { sv[i >> 3] = v; si[i >> 3] = (short)(i >> 3); }
    }
    __syncthreads();
    for (int k = 2; k <= 2048; k <<= 1) {
        for (int j = k >> 1; j > 0; j >>= 1) {
            for (int i = tid; i < 2048; i += 1024) {
                int ixj = i ^ j;
                if (ixj > i) {
                    bool up = ((i & k) == 0);
                    float vi = sv[i], vx = sv[ixj];
                    bool swap = up ? (vi > vx) : (vi < vx);
                    if (swap) {
                        sv[i] = vx; sv[ixj] = vi;
                        short t = si[i]; si[i] = si[ixj]; si[ixj] = t;
                    }
                }
            }
            __syncthreads();
        }
    }
    int i1, i2, i3;
    if (tid == 0) cnt = 0;
    __syncthreads();
    { int lc = 0;
      for (int i = tid; i < 2048; i += 1024) lc += (sv[i] < P_T1);
      for (int off = 16; off; off >>= 1) lc += __shfl_xor_sync(~0u, lc, off);
      if ((tid & 31) == 0) atomicAdd(&cnt, lc); }
    __syncthreads();
    i1 = cnt;
    for (int i = tid; i < 2048; i += 1024)
        if (i < i1 - 1) sv[i] = P_A1 * sv[i] + P_B1;
    __syncthreads();
    if (tid == 0) cnt = 0;
    __syncthreads();
    { int lc = 0;
      for (int i = tid; i < 2048; i += 1024) lc += (sv[i] < 0.f);
      for (int off = 16; off; off >>= 1) lc += __shfl_xor_sync(~0u, lc, off);
      if ((tid & 31) == 0) atomicAdd(&cnt, lc); }
    __syncthreads();
    i2 = cnt;
    for (int i = tid; i < 2048; i += 1024)
        if (i >= i1 && i < i2 - 1) sv[i] = P_A2 * sv[i] + P_B2;
    __syncthreads();
    if (tid == 0) cnt = 0;
    __syncthreads();
    { int lc = 0;
      for (int i = tid; i < 2048; i += 1024) lc += (sv[i] < P_T3);
      for (int off = 16; off; off >>= 1) lc += __shfl_xor_sync(~0u, lc, off);
      if ((tid & 31) == 0) atomicAdd(&cnt, lc); }
    __syncthreads();
    i3 = cnt;
    for (int i = tid; i < 2048; i += 1024) {
        float v = sv[i];
        if (i >= i2 && i < i3 - 1) v = P_A3 * v + P_B3;
        if (i >= i3 && i < 2047)   v = P_A4 * v + P_B4;
        int oi = si[i];
        const float4* up = (const float4*)&g_u[((size_t)b * NRT + oi) * DI];
        float4 a0 = up[0], a1 = up[1];
        a0.x *= v; a0.y *= v; a0.z *= v; a0.w *= v;
        a1.x *= v; a1.y *= v; a1.z *= v; a1.w *= v;
        float4* op = (float4*)&g_us[((size_t)b * NRT + oi) * DI];
        op[0] = a0; op[1] = a1;
    }
}

// ---------------- routing: fused softmax + s_j ----------------
__global__ void __launch_bounds__(256, 1)
sj_fused_kernel(const float* __restrict__ W) {
    extern __shared__ float sh[];
    float* Ws   = sh;                    // 20480
    float* us_s = sh + 20480;            // 13600
    float* cs   = sh + 34080;            // 160
    float* mxs  = sh + 34240;            // 16
    float* sms  = sh + 34256;            // 16
    float* red2 = sh + 34272;            // 256*11
    int tid = threadIdx.x;
    int r0 = blockIdx.x * 16;

    {
        float pm[10];
        #pragma unroll
        for (int c = 0; c < 10; c++) pm[c] = -1e30f;
        for (int r = tid; r < NRT; r += 256) {
            const float* row = g_bij + r * 10;
            #pragma unroll
            for (int c = 0; c < 10; c++) pm[c] = fmaxf(pm[c], row[c]);
        }
        #pragma unroll
        for (int c = 0; c < 10; c++) red2[tid * 11 + c] = pm[c];
        __syncthreads();
        if (tid < 10) {
            float m = -1e30f;
            for (int t = 0; t < 256; t++) m = fmaxf(m, red2[t * 11 + tid]);
            mxs[tid] = m;
        }
        __syncthreads();
        float ps[10];
        #pragma unroll
        for (int c = 0; c < 10; c++) ps[c] = 0.f;
        for (int r = tid; r < NRT; r += 256) {
            const float* row = g_bij + r * 10;
            #pragma unroll
            for (int c = 0; c < 10; c++) ps[c] += expf(row[c] - mxs[c]);
        }
        #pragma unroll
        for (int c = 0; c < 10; c++) red2[tid * 11 + c] = ps[c];
        __syncthreads();
        if (tid < 10) {
            float s = 0.f;
            for (int t = 0; t < 256; t++) s += red2[t * 11 + tid];
            sms[tid] = s;
        }
        __syncthreads();
        for (int j = tid; j < 160; j += 256) {
            int rl = j / 10, c = j - rl * 10;
            cs[rl * 10 + c] = expf(g_bij[(r0 + rl) * 10 + c] - mxs[c]) / sms[c];
        }
    }

    {
        const float4* wsrc = (const float4*)(W + (size_t)r0 * 1280);
        float4* wdst = (float4*)Ws;
        for (int j = tid; j < 5120; j += 256) wdst[j] = wsrc[j];
        for (int j = tid; j < 3200; j += 256) {
            int b = j >> 5, rem = j & 31;
            int rl = rem >> 1, q = rem & 1;
            *(float4*)&us_s[b * 136 + rl * 8 + q * 4] =
                *(const float4*)&g_us[(size_t)b * 16384 + (r0 + rl) * 8 + q * 4];
        }
    }
    __syncthreads();

    if (tid < 250) {
        int c = tid / 25, bq = tid % 25;
        float acc[4][16];
        #pragma unroll
        for (int bb = 0; bb < 4; bb++)
            #pragma unroll
            for (int o = 0; o < 16; o++) acc[bb][o] = 0.f;

        for (int rl = 0; rl < 16; rl++) {
            float cw = cs[rl * 10 + c];
            float up[4][8];
            #pragma unroll
            for (int bb = 0; bb < 4; bb++) {
                int b = bq + 25 * bb;
                float4 u0 = *(float4*)&us_s[b * 136 + rl * 8];
                float4 u1 = *(float4*)&us_s[b * 136 + rl * 8 + 4];
                up[bb][0] = cw * u0.x; up[bb][1] = cw * u0.y;
                up[bb][2] = cw * u0.z; up[bb][3] = cw * u0.w;
                up[bb][4] = cw * u1.x; up[bb][5] = cw * u1.y;
                up[bb][6] = cw * u1.z; up[bb][7] = cw * u1.w;
            }
            const float* wrow = &Ws[rl * 1280 + c * 128];
            #pragma unroll
            for (int o = 0; o < 16; o++) {
                float4 w0 = *(const float4*)&wrow[o * 8];
                float4 w1 = *(const float4*)&wrow[o * 8 + 4];
                #pragma unroll
                for (int bb = 0; bb < 4; bb++) {
                    acc[bb][o] += w0.x * up[bb][0] + w0.y * up[bb][1]
                                + w0.z * up[bb][2] + w0.w * up[bb][3]
                                + w1.x * up[bb][4] + w1.y * up[bb][5]
                                + w1.z * up[bb][6] + w1.w * up[bb][7];
                }
            }
        }
        float* sp = g_spart + (size_t)blockIdx.x * 16000;
        #pragma unroll
        for (int bb = 0; bb < 4; bb++) {
            int b = bq + 25 * bb;
            #pragma unroll
            for (int o = 0; o < 16; o++)
                sp[b * 160 + c * 16 + o] = acc[bb][o];
        }
    }
}

// ---------------- digit: reduce partials + 10-sort + squash + v_j ----------------
__global__ void digit_kernel() {
    __shared__ float sj[160];
    __shared__ float f[10];
    int b = blockIdx.x, t = threadIdx.x;
    {
        float s = 0.f;
        const float* sp = g_spart + b * 160 + t;
        #pragma unroll 4
        for (int ch = 0; ch < 128; ch++) s += sp[(size_t)ch * 16000];
        sj[t] = s;
    }
    __syncthreads();
    if (t == 0) {
        float v[10]; int id[10];
        #pragma unroll
        for (int c = 0; c < 10; c++) { v[c] = sj[c * 16]; id[c] = c; }
        for (int i = 1; i < 10; i++) {
            float kv = v[i]; int ki = id[i]; int j = i - 1;
            while (j >= 0 && v[j] > kv) { v[j+1] = v[j]; id[j+1] = id[j]; j--; }
            v[j+1] = kv; id[j+1] = ki;
        }
        int i1 = 0, i2 = 0, i3 = 0;
        #pragma unroll
        for (int k = 0; k < 10; k++) i1 += (v[k] < D_T1);
        #pragma unroll
        for (int k = 0; k < 10; k++) if (k < i1 - 1) v[k] = D_A1 * v[k] + D_B1;
        #pragma unroll
        for (int k = 0; k < 10; k++) i2 += (v[k] < 0.f);
        #pragma unroll
        for (int k = 0; k < 10; k++) if (k >= i1 && k < i2 - 1) v[k] = D_A2 * v[k] + D_B2;
        #pragma unroll
        for (int k = 0; k < 10; k++) i3 += (v[k] < D_T3);
        #pragma unroll
        for (int k = 0; k < 10; k++) if (k >= i2 && k < i3 - 1) v[k] = D_A3 * v[k] + D_B3;
        #pragma unroll
        for (int k = 0; k < 10; k++) if (k >= i3 && k < 9) v[k] = D_A4 * v[k] + D_B4;
        #pragma unroll
        for (int k = 0; k < 10; k++) f[id[k]] = v[k];
    }
    __syncthreads();
    {
        int c = t >> 4, o = t & 15;
        float fc = f[c];
        g_vj[b * 160 + t] = fc * ((o == 0) ? fc : sj[t]);
    }
}

// ---------------- routing: fused agreement ----------------
__global__ void __launch_bounds__(256, 1)
agree_fused_kernel(const float* __restrict__ W) {
    extern __shared__ float sh[];
    float* Ws   = sh;            // 10240
    float* us_s = sh + 10240;    // 6800
    float* v_s  = sh + 17040;    // 16400
    float* red  = sh + 33440;    // 256
    int tid = threadIdx.x;
    int r0 = blockIdx.x * 8;

    {
        const float4* wsrc = (const float4*)(W + (size_t)r0 * 1280);
        float4* wdst = (float4*)Ws;
        for (int j = tid; j < 2560; j += 256) wdst[j] = wsrc[j];
        for (int j = tid; j < 1600; j += 256) {
            int b = j >> 4, rem = j & 15, rl = rem >> 1, q = rem & 1;
            *(float4*)&us_s[b * 68 + rl * 8 + q * 4] =
                *(const float4*)&g_us[(size_t)b * 16384 + (r0 + rl) * 8 + q * 4];
        }
        for (int j = tid; j < 4000; j += 256) {
            int b = j / 40, rem = j - b * 40;
            *(float4*)&v_s[b * 164 + rem * 4] =
                *(const float4*)&g_vj[b * 160 + rem * 4];
        }
    }
    __syncthreads();

    int c = tid / 25, bq = tid % 25;
    for (int rl = 0; rl < 8; rl++) {
        if (tid < 250) {
            float pa = 0.f;
            const float* wrow = &Ws[rl * 1280 + c * 128];
            #pragma unroll
            for (int bb = 0; bb < 4; bb++) {
                int b = bq + 25 * bb;
                float4 u0 = *(float4*)&us_s[b * 68 + rl * 8];
                float4 u1 = *(float4*)&us_s[b * 68 + rl * 8 + 4];
                #pragma unroll
                for (int og = 0; og < 4; og++) {
                    float vv[4];
                    *(float4*)vv = *(float4*)&v_s[b * 164 + c * 16 + og * 4];
                    #pragma unroll
                    for (int oo = 0; oo < 4; oo++) {
                        int o = og * 4 + oo;
                        float4 w0 = *(const float4*)&wrow[o * 8];
                        float4 w1 = *(const float4*)&wrow[o * 8 + 4];
                        float d = w0.x * u0.x + w0.y * u0.y + w0.z * u0.z + w0.w * u0.w
                                + w1.x * u1.x + w1.y * u1.y + w1.z * u1.z + w1.w * u1.w;
                        pa += d * vv[oo];
                    }
                }
            }
            red[tid] = pa;
        }
        __syncthreads();
        if (tid < 10) {
            float s = 0.f;
            #pragma unroll
            for (int q = 0; q < 25; q++) s += red[tid * 25 + q];
            g_bij[(r0 + rl) * 10 + tid] += s * 0.01f;
        }
        __syncthreads();
    }
}

// ---------------- decoder: mask + dec1 fused (grid 100, 512 threads) ----------------
__global__ void maskdec1_kernel(const float* __restrict__ w1,
                                const float* __restrict__ b1,
                                float* __restrict__ out) {
    __shared__ float cls[PB * NCAP];
    __shared__ float cmx[NCAP], csm[NCAP];
    __shared__ int sidx;
    int b = blockIdx.x, tid = threadIdx.x;
    for (int j = tid; j < PB * NCAP; j += 512) {
        float s = 0.f;
        const float* vp = g_vj + j * 16;
        #pragma unroll
        for (int o = 0; o < 16; o++) s += vp[o] * vp[o];
        cls[j] = sqrtf(s);
    }
    __syncthreads();
    if (tid < NCAP) {
        float m = -1e30f;
        for (int bb = 0; bb < PB; bb++) m = fmaxf(m, cls[bb * NCAP + tid]);
        float s = 0.f;
        for (int bb = 0; bb < PB; bb++) s += expf(cls[bb * NCAP + tid] - m);
        cmx[tid] = m; csm[tid] = s;
    }
    __syncthreads();
    if (tid == 0) {
        float best = -1e30f; int bi = 0;
        for (int c = 0; c < NCAP; c++) {
            float p = expf(cls[b * NCAP + c] - cmx[c]) / csm[c];
            if (p > best) { best = p; bi = c; }
        }
        sidx = bi;
    }
    __syncthreads();
    if (tid < 160) out[(size_t)b * 1184 + tid] = g_vj[b * 160 + tid];
    {
        int id = sidx;
        const float* v = g_vj + (b * NCAP + id) * 16;
        const float* wr = w1 + (size_t)tid * 160 + id * 16;
        float acc = b1[tid];
        #pragma unroll
        for (int o = 0; o < 16; o++) acc += v[o] * wr[o];
        g_h1[b * 512 + tid] = fmaxf(acc, 0.f);
    }
}

// 4 batches per block; grid (4 jchunks, 25 bgroups)
__global__ void dec2_kernel(const float* __restrict__ w2,
                            const float* __restrict__ b2) {
    __shared__ float h1s[4 * 512];
    int tid = threadIdx.x;
    int jc = blockIdx.x, bg = blockIdx.y;
    for (int i = tid; i < 2048; i += 256)
        h1s[i] = g_h1[(bg * 4 + (i >> 9)) * 512 + (i & 511)];
    __syncthreads();
    int j = jc * 256 + tid;
    const float4* wr = (const float4*)(w2 + (size_t)j * 512);
    float acc[4] = {0.f, 0.f, 0.f, 0.f};
    #pragma unroll 4
    for (int k = 0; k < 128; k++) {
        float4 wv = wr[k];
        #pragma unroll
        for (int bb = 0; bb < 4; bb++) {
            const float* hp = &h1s[bb * 512 + 4 * k];
            acc[bb] += wv.x * hp[0] + wv.y * hp[1] + wv.z * hp[2] + wv.w * hp[3];
        }
    }
    float bv = b2[j];
    #pragma unroll
    for (int bb = 0; bb < 4; bb++)
        g_h2[(bg * 4 + bb) * 1024 + j] = fmaxf(acc[bb] + bv, 0.f);
}

// 4 batches per block; grid (4 jchunks, 25 bgroups)
__global__ void dec3_kernel(const float* __restrict__ w3,
                            const float* __restrict__ b3,
                            float* __restrict__ out) {
    __shared__ float h2s[4 * 1024];
    int tid = threadIdx.x;
    int jc = blockIdx.x, bg = blockIdx.y;
    for (int i = tid; i < 4096; i += 256)
        h2s[i] = g_h2[(bg * 4 + (i >> 10)) * 1024 + (i & 1023)];
    __syncthreads();
    int j = jc * 256 + tid;
    const float4* wr = (const float4*)(w3 + (size_t)j * 1024);
    float acc[4] = {0.f, 0.f, 0.f, 0.f};
    #pragma unroll 4
    for (int k = 0; k < 256; k++) {
        float4 wv = wr[k];
        #pragma unroll
        for (int bb = 0; bb < 4; bb++) {
            const float* hp = &h2s[bb * 1024 + 4 * k];
            acc[bb] += wv.x * hp[0] + wv.y * hp[1] + wv.z * hp[2] + wv.w * hp[3];
        }
    }
    float bv = b3[j];
    #pragma unroll
    for (int bb = 0; bb < 4; bb++) {
        float z = acc[bb] + bv;
        out[(size_t)(bg * 4 + bb) * 1184 + 160 + j] = 1.f / (1.f + expf(-z));
    }
}

// ---------------- launch ----------------
extern "C" void kernel_launch(void* const* d_in, const int* in_sizes, int n_in,
                              void* d_out, int out_size) {
    const float* data    = (const float*)d_in[0];
    const float* conv1_w = (const float*)d_in[1];
    const float* conv1_b = (const float*)d_in[2];
    const float* prim_w  = (const float*)d_in[3];
    const float* prim_b  = (const float*)d_in[4];
    const float* W_dc    = (const float*)d_in[5];
    const float* dec_w1  = (const float*)d_in[6];
    const float* dec_b1  = (const float*)d_in[7];
    const float* dec_w2  = (const float*)d_in[8];
    const float* dec_b2  = (const float*)d_in[9];
    const float* dec_w3  = (const float*)d_in[10];
    const float* dec_b3  = (const float*)d_in[11];
    float* out = (float*)d_out;

    cudaFuncSetAttribute(prim_mma_kernel,
                         cudaFuncAttributeMaxDynamicSharedMemorySize, SMEM_TOTAL);
    cudaFuncSetAttribute(wsplit_kernel,
                         cudaFuncAttributeMaxDynamicSharedMemorySize, KTOT * 4);
    cudaFuncSetAttribute(conv1_kernel,
                         cudaFuncAttributeMaxDynamicSharedMemorySize, CV_SMEM);
    cudaFuncSetAttribute(sj_fused_kernel,
                         cudaFuncAttributeMaxDynamicSharedMemorySize, SJ_SMEM);
    cudaFuncSetAttribute(agree_fused_kernel,
                         cudaFuncAttributeMaxDynamicSharedMemorySize, AG_SMEM);

    // prim_mma in ncu capture slot (#4)
    wsplit_kernel<<<256, 256, KTOT * 4>>>(prim_w);
    conv1_kernel<<<dim3(100, 8), 256, CV_SMEM>>>(data, conv1_w, conv1_b);
    initbij_kernel<<<80, 256>>>();
    prim_mma_kernel<<<dim3(100, 2, 2), 256, SMEM_TOTAL>>>();
    mag_kernel<<<100, 1024>>>(prim_b);

    for (int it = 0; it < 3; it++) {
        sj_fused_kernel<<<128, 256, SJ_SMEM>>>(W_dc);
        digit_kernel<<<100, 160>>>();
        if (it < 2) agree_fused_kernel<<<256, 256, AG_SMEM>>>(W_dc);
    }

    maskdec1_kernel<<<100, 512>>>(dec_w1, dec_b1, out);
    dec2_kernel<<<dim3(4, 25), 256>>>(dec_w2, dec_b2);
    dec3_kernel<<<dim3(4, 25), 256>>>(dec_w3, dec_b3, out);
}